// round 6
// baseline (speedup 1.0000x reference)
#include <cuda_runtime.h>
#include <cuda_bf16.h>
#include <cstdint>

#define LV       4087
#define BROWS    2048
#define NSTEP    1021
#define NCH      4096
#define EPSF     1e-6f
#define CSTRIDE  4096
#define PADSTEP  1032

// 67.6 MB coefficient scratch, [step][chain]: {-l*ct, l*st*cos(chi), l*st*sin(chi), 0}
__device__ float4 g_coef[(size_t)PADSTEP * NCH];
__device__ float4 g_init[NCH];   // {l1, -l2*ct0, l2*st0, 0}
__device__ double g_acc;
__device__ unsigned g_count;

__device__ __forceinline__ float dnbl(float v) { return ((v + 1.0f) * 0.5f) * 2.1f + 0.9f; }
__device__ __forceinline__ float dnd (float v) { return ((v + 1.0f) * 0.5f) * 3.5f + 1.5f; }
__device__ __forceinline__ float clip1(float v) { return fminf(fmaxf(v, -1.0f), 1.0f); }

__device__ __forceinline__ float rsq_approx(float x) {
    float y; asm("rsqrt.approx.f32 %0, %1;" : "=f"(y) : "f"(x)); return y;
}
__device__ __forceinline__ float rcp_approx(float x) {
    float y; asm("rcp.approx.f32 %0, %1;" : "=f"(y) : "f"(x)); return y;
}
__device__ __forceinline__ float sqrt_approx(float x) {
    float y; asm("sqrt.approx.f32 %0, %1;" : "=f"(y) : "f"(x)); return y;  // sqrt(0)=0, no NaN
}

// ---------------------------------------------------------------------------
// Prep: lane = step (coalesced reads), smem transpose, coalesced writes.
// Also folds in per-chain init (j-tile 0) and the accumulator reset.
// ---------------------------------------------------------------------------
__global__ __launch_bounds__(1024) void prep_kernel(const float* __restrict__ pred,
                                                    const float* __restrict__ targ)
{
    __shared__ float4 T[32][33];
    const int tx = threadIdx.x;            // step offset in tile
    const int ty = threadIdx.y;            // chain offset in tile
    const int J0 = blockIdx.x * 32;
    const int C0 = blockIdx.y * 32;
    const int c  = C0 + ty;
    const int j  = J0 + tx;
    const int row = c & (BROWS - 1);
    const bool isP = c < BROWS;
    const float* __restrict__ v = (isP ? pred : targ) + (size_t)row * LV;

    if (blockIdx.x == 0 && blockIdx.y == 0 && tx == 0 && ty == 0) {
        g_acc = 0.0;
        g_count = 0u;
    }

    // fold init: chain geometry for atoms 1,2
    if (blockIdx.x == 0 && tx == 0) {
        float b0 = v[3064], b1 = v[3065], dr = v[2042];
        if (isP) { b0 = clip1(b0); b1 = clip1(b1); dr = clip1(dr); }
        float l1 = dnbl(b0), l2 = dnbl(b1), dd = dnd(dr);
        float ct = (l1 * l1 + l2 * l2 - dd * dd) / (2.0f * l1 * l2);
        ct = fminf(fmaxf(ct, -1.0f + EPSF), 1.0f - EPSF);
        float st = sqrtf((1.0f - ct) * (1.0f + ct));
        g_init[c] = make_float4(l1, -l2 * ct, l2 * st, 0.0f);
    }

    float4 o = make_float4(0.f, 0.f, 0.f, 0.f);
    if (j < NSTEP) {
        float b1r = v[3064 + j + 1];
        float b2r = v[3064 + j + 2];
        float dr  = v[2042 + j + 1];
        float s0  = v[2 * j];
        float s1  = v[2 * j + 1];
        if (isP) {
            b1r = clip1(b1r); b2r = clip1(b2r); dr = clip1(dr);
            s0 = clip1(s0);   s1 = clip1(s1);
        }
        float l1 = dnbl(b1r), l = dnbl(b2r), dd = dnd(dr);
        float ct = (l1 * l1 + l * l - dd * dd) / (2.0f * l1 * l);
        ct = fminf(fmaxf(ct, -1.0f + EPSF), 1.0f - EPSF);
        float st = sqrtf((1.0f - ct) * (1.0f + ct));

        float h2 = s0 * s0 + s1 * s1;
        float cch, sch;
        if (h2 < 1e-30f) { cch = 1.0f; sch = 0.0f; }
        else { float rh = rsqrtf(h2); cch = s1 * rh; sch = s0 * rh; }

        o.x = -l * ct;
        o.y =  l * st * cch;
        o.z =  l * st * sch;
    }
    T[ty][tx] = o;
    __syncthreads();

    int jo = J0 + ty;
    if (jo < 1024)
        g_coef[(size_t)jo * CSTRIDE + (C0 + tx)] = T[tx][ty];
}

// ---------------------------------------------------------------------------
// Scan step. State: u2 (last bond), q12 = u1 x u2, position c, plus scalars
// A2 = |u2|^2 (TRUE dot of stored u2), inv1 ~ 1/(|u2|+eps),
// rcpn ~ 1/(|q12| + eps*|u2|) — both computed LAST step from actual vectors,
// so normalization is always exact w.r.t. real state (self-correcting; no
// exponential drift), while the MUFU latencies hide behind the step tail.
//   e    = s1*u2 + s2*(q12 x u2) + s3*q12
//   q12' = u2 x e = (s2*A2)*q12 - s3*(q12 x u2)   [exact; A2 is true |u2|^2]
// ---------------------------------------------------------------------------
__device__ __forceinline__ void step_fn(const float4 cf,
    float& u2x, float& u2y, float& u2z,
    float& q12x, float& q12y, float& q12z,
    float& cx, float& cy, float& cz,
    float& A2, float& inv1, float& rcpn,
    float& accx, float& accy, float& accz)
{
    // scalars (inv1/rcpn precomputed from previous step's actual vectors)
    float s1 = cf.x * inv1;
    float s3 = cf.z * rcpn;
    float s2 = (cf.y * inv1) * rcpn;

    // cxu = q12 x u2
    float cxux = fmaf(q12y, u2z, -q12z * u2y);
    float cxuy = fmaf(q12z, u2x, -q12x * u2z);
    float cxuz = fmaf(q12x, u2y, -q12y * u2x);

    // new bond e and position d
    float ex = fmaf(s1, u2x, fmaf(s2, cxux, s3 * q12x));
    float ey = fmaf(s1, u2y, fmaf(s2, cxuy, s3 * q12y));
    float ez = fmaf(s1, u2z, fmaf(s2, cxuz, s3 * q12z));
    float dx = cx + ex, dy = cy + ey, dz = cz + ez;

    // q12' = (s2*A2)*q12 - s3*cxu
    float g = s2 * A2;
    float n12x = fmaf(g, q12x, -s3 * cxux);
    float n12y = fmaf(g, q12y, -s3 * cxuy);
    float n12z = fmaf(g, q12z, -s3 * cxuz);

    // TRUE norms of the new stored vectors (self-correcting)
    float A2n = fmaf(ex, ex, fmaf(ey, ey, ez * ez));
    float C2n = fmaf(n12x, n12x, fmaf(n12y, n12y, n12z * n12z));

    // next-step inverses; MUFU latency hides behind shfl/acc/prefetch tail
    float rA  = rsq_approx(A2n);                 // A2n >= ~0.8, never 0
    float i1n = fmaf(-EPSF * rA, rA, rA);        // 1/(|e|+eps) to O(eps^2)
    float an  = A2n * rA;                        // |e|
    float ncn = sqrt_approx(C2n);                // |q12'|, safe at 0
    float rcn = rcp_approx(fmaf(EPSF, an, ncn)); // 1/(|q12'| + eps*|e|)

    // commit state
    u2x = ex;  u2y = ey;  u2z = ez;
    q12x = n12x; q12y = n12y; q12z = n12z;
    cx = dx;   cy = dy;   cz = dz;
    A2 = A2n;  inv1 = i1n; rcpn = rcn;

    // loss pairing (pred lane i <-> targ lane i+16), 3 independent accumulators
    float ox = __shfl_xor_sync(0xffffffffu, dx, 16);
    float oy = __shfl_xor_sync(0xffffffffu, dy, 16);
    float oz = __shfl_xor_sync(0xffffffffu, dz, 16);
    float fx = dx - ox, fy = dy - oy, fz = dz - oz;
    accx = fmaf(fx, fx, accx);
    accy = fmaf(fy, fy, accy);
    accz = fmaf(fz, fz, accz);
}

__global__ void __launch_bounds__(32) scan_kernel(float* __restrict__ out)
{
    int lane  = threadIdx.x;
    int row   = blockIdx.x * 16 + (lane & 15);
    int chain = row + ((lane >> 4) << 11);   // +2048 for targ half

    float4 ini = g_init[chain];
    float u1x = ini.x;                           // a1-a0 = (l1,0,0)
    float u2x = ini.y, u2y = ini.z, u2z = 0.f;   // a2-a1
    float cx = ini.x + ini.y, cy = ini.z, cz = 0.f;

    // q12 = u1 x u2 = (0, 0, l1*u2y)
    float q12x = 0.f, q12y = 0.f, q12z = u1x * u2y;
    float A2 = fmaf(u2x, u2x, u2y * u2y);
    float a  = sqrtf(A2);
    float inv1 = 1.0f / (a + EPSF);
    float rcpn = 1.0f / (fabsf(q12z) + EPSF * a);

    float accx = 0.f, accy = 0.f, accz = 0.f;

    // atoms 1 and 2 (atom 0 identical on both sides)
    {
        float o1 = __shfl_xor_sync(0xffffffffu, u1x, 16);
        float o2 = __shfl_xor_sync(0xffffffffu, cx, 16);
        float o3 = __shfl_xor_sync(0xffffffffu, cy, 16);
        float f1 = u1x - o1, f2 = cx - o2, f3 = cy - o3;
        accx = fmaf(f1, f1, accx);
        accy = fmaf(f2, f2, accy);
        accz = fmaf(f3, f3, accz);
    }

    const float4* p = g_coef + chain;
    float4 buf[8];
#pragma unroll
    for (int u = 0; u < 8; ++u) buf[u] = __ldg(p + (size_t)u * CSTRIDE);

#pragma unroll 1
    for (int g = 0; g < 127; ++g) {          // 127*8 = 1016 steps
        const float4* pn = p + (size_t)8 * CSTRIDE;
#pragma unroll
        for (int u = 0; u < 8; ++u) {
            float4 cf = buf[u];
            buf[u] = __ldg(pn + (size_t)u * CSTRIDE);
            step_fn(cf, u2x, u2y, u2z, q12x, q12y, q12z, cx, cy, cz,
                    A2, inv1, rcpn, accx, accy, accz);
        }
        p = pn;
    }
#pragma unroll
    for (int u = 0; u < 5; ++u)              // steps 1016..1020
        step_fn(buf[u], u2x, u2y, u2z, q12x, q12y, q12z, cx, cy, cz,
                A2, inv1, rcpn, accx, accy, accz);

    float acc = accx + accy + accz;
#pragma unroll
    for (int off = 16; off > 0; off >>= 1)
        acc += __shfl_xor_sync(0xffffffffu, acc, off);

    if (lane == 0) {
        atomicAdd(&g_acc, (double)acc);
        __threadfence();
        unsigned old = atomicAdd(&g_count, 1u);
        if (old == (unsigned)(gridDim.x - 1)) {
            double total;
            asm volatile("ld.global.cg.f64 %0, [%1];" : "=d"(total) : "l"(&g_acc));
            // halves duplicated -> /2; mean over 2048*1024*3
            out[0] = (float)(total * (1.0 / (2.0 * 2048.0 * 1024.0 * 3.0)));
        }
    }
}

extern "C" void kernel_launch(void* const* d_in, const int* in_sizes, int n_in,
                              void* d_out, int out_size)
{
    const float* pred = (const float*)d_in[0];
    const float* targ = (const float*)d_in[1];
    float* out = (float*)d_out;

    dim3 pb(32, 32), pg(32, NCH / 32);
    prep_kernel<<<pg, pb>>>(pred, targ);
    scan_kernel<<<BROWS / 16, 32>>>(out);
}

// round 7
// speedup vs baseline: 1.1172x; 1.1172x over previous
#include <cuda_runtime.h>
#include <cuda_bf16.h>
#include <cstdint>

#define LV       4087
#define BROWS    2048
#define NSTEP    1021
#define NCH      4096
#define EPSF     1e-6f
#define CSTRIDE  4096
#define PADSTEP  1032
#define NROWS    1023            // atoms 1..1023 stored
#define NPAIR    (NROWS * BROWS)

// [step][chain] coefficients: {-l*ct, l*st*cos(chi), l*st*sin(chi), 0}  (67.6MB)
__device__ float4 g_coef[(size_t)PADSTEP * NCH];
// [atom-1][chain] positions, atoms 1..1023 (67MB)
__device__ float4 g_pos[(size_t)NROWS * NCH];
__device__ float4 g_init[NCH];   // {l1, -l2*ct0, l2*st0, 0}
__device__ double g_acc;
__device__ unsigned g_count;

__device__ __forceinline__ float dnbl(float v) { return ((v + 1.0f) * 0.5f) * 2.1f + 0.9f; }
__device__ __forceinline__ float dnd (float v) { return ((v + 1.0f) * 0.5f) * 3.5f + 1.5f; }
__device__ __forceinline__ float clip1(float v) { return fminf(fmaxf(v, -1.0f), 1.0f); }

__device__ __forceinline__ float rsq_approx(float x) {
    float y; asm("rsqrt.approx.f32 %0, %1;" : "=f"(y) : "f"(x)); return y;
}

// ---------------------------------------------------------------------------
// Prep: lane = step (coalesced reads), smem transpose, coalesced writes.
// Folds per-chain init + accumulator reset.
// ---------------------------------------------------------------------------
__global__ __launch_bounds__(1024) void prep_kernel(const float* __restrict__ pred,
                                                    const float* __restrict__ targ)
{
    __shared__ float4 T[32][33];
    const int tx = threadIdx.x;
    const int ty = threadIdx.y;
    const int J0 = blockIdx.x * 32;
    const int C0 = blockIdx.y * 32;
    const int c  = C0 + ty;
    const int j  = J0 + tx;
    const int row = c & (BROWS - 1);
    const bool isP = c < BROWS;
    const float* __restrict__ v = (isP ? pred : targ) + (size_t)row * LV;

    if (blockIdx.x == 0 && blockIdx.y == 0 && tx == 0 && ty == 0) {
        g_acc = 0.0;
        g_count = 0u;
    }

    if (blockIdx.x == 0 && tx == 0) {
        float b0 = v[3064], b1 = v[3065], dr = v[2042];
        if (isP) { b0 = clip1(b0); b1 = clip1(b1); dr = clip1(dr); }
        float l1 = dnbl(b0), l2 = dnbl(b1), dd = dnd(dr);
        float ct = (l1 * l1 + l2 * l2 - dd * dd) / (2.0f * l1 * l2);
        ct = fminf(fmaxf(ct, -1.0f + EPSF), 1.0f - EPSF);
        float st = sqrtf((1.0f - ct) * (1.0f + ct));
        g_init[c] = make_float4(l1, -l2 * ct, l2 * st, 0.0f);
    }

    float4 o = make_float4(0.f, 0.f, 0.f, 0.f);
    if (j < NSTEP) {
        float b1r = v[3064 + j + 1];
        float b2r = v[3064 + j + 2];
        float dr  = v[2042 + j + 1];
        float s0  = v[2 * j];
        float s1  = v[2 * j + 1];
        if (isP) {
            b1r = clip1(b1r); b2r = clip1(b2r); dr = clip1(dr);
            s0 = clip1(s0);   s1 = clip1(s1);
        }
        float l1 = dnbl(b1r), l = dnbl(b2r), dd = dnd(dr);
        float ct = (l1 * l1 + l * l - dd * dd) / (2.0f * l1 * l);
        ct = fminf(fmaxf(ct, -1.0f + EPSF), 1.0f - EPSF);
        float st = sqrtf((1.0f - ct) * (1.0f + ct));

        float h2 = s0 * s0 + s1 * s1;
        float cch, sch;
        if (h2 < 1e-30f) { cch = 1.0f; sch = 0.0f; }
        else { float rh = rsqrtf(h2); cch = s1 * rh; sch = s0 * rh; }

        o.x = -l * ct;
        o.y =  l * st * cch;
        o.z =  l * st * sch;
    }
    T[ty][tx] = o;
    __syncthreads();

    int jo = J0 + ty;
    if (jo < 1024)
        g_coef[(size_t)jo * CSTRIDE + (C0 + tx)] = T[tx][ty];
}

// ---------------------------------------------------------------------------
// Scan step (Round-3 math: in-step true norms, self-correcting), no shfl:
//   c12 = u1 x u2 ; cxu = c12 x u2 ; A2=|u2|^2 ; C2=|c12|^2
//   inv1 ~ 1/(|u2|+eps)          (rsqrt + eps fold)
//   rcpD ~ 1/(|c12| + eps*|u2|)  (rsqrt + first-order fold; == inv1*inv2)
//   e = s1*u2 + s2*cxu + s3*c12 ; position streamed out via STG.128.
// ---------------------------------------------------------------------------
__device__ __forceinline__ void step_fn(const float4 cf,
    float& u1x, float& u1y, float& u1z,
    float& u2x, float& u2y, float& u2z,
    float& cx, float& cy, float& cz,
    float4* __restrict__ outp)
{
    float c12x = fmaf(u1y, u2z, -u1z * u2y);
    float c12y = fmaf(u1z, u2x, -u1x * u2z);
    float c12z = fmaf(u1x, u2y, -u1y * u2x);

    float cxux = fmaf(c12y, u2z, -c12z * u2y);
    float cxuy = fmaf(c12z, u2x, -c12x * u2z);
    float cxuz = fmaf(c12x, u2y, -c12y * u2x);

    float A2 = fmaf(u2x, u2x, fmaf(u2y, u2y, u2z * u2z));
    float C2 = fmaf(c12x, c12x, fmaf(c12y, c12y, c12z * c12z));

    float r1   = rsq_approx(A2);
    float inv1 = fmaf(-EPSF * r1, r1, r1);      // 1/(|u2|+eps)
    float an   = A2 * r1;                       // |u2|
    float rC   = rsq_approx(C2);                // 1/|c12|
    float t    = an * rC;
    float rcpD = fmaf(-EPSF * t, rC, rC);       // 1/(|c12|+eps*|u2|)

    float s1 = cf.x * inv1;
    float s3 = cf.z * rcpD;
    float s2 = (cf.y * inv1) * rcpD;

    float ex = fmaf(s1, u2x, fmaf(s2, cxux, s3 * c12x));
    float ey = fmaf(s1, u2y, fmaf(s2, cxuy, s3 * c12y));
    float ez = fmaf(s1, u2z, fmaf(s2, cxuz, s3 * c12z));

    float dx = cx + ex, dy = cy + ey, dz = cz + ez;
    u1x = u2x; u1y = u2y; u1z = u2z;
    u2x = ex;  u2y = ey;  u2z = ez;
    cx = dx;   cy = dy;   cz = dz;

    *outp = make_float4(dx, dy, dz, 0.0f);
}

__global__ void __launch_bounds__(32) scan_kernel()
{
    int lane  = threadIdx.x;
    int chain = blockIdx.x * 32 + lane;

    float4 ini = g_init[chain];
    float u1x = ini.x, u1y = 0.f, u1z = 0.f;       // a1-a0
    float u2x = ini.y, u2y = ini.z, u2z = 0.f;     // a2-a1
    float cx = ini.x + ini.y, cy = ini.z, cz = 0.f;

    float4* op = g_pos + chain;
    op[0]                 = make_float4(ini.x, 0.f, 0.f, 0.f);  // atom 1
    op[(size_t)CSTRIDE]   = make_float4(cx, cy, 0.f, 0.f);      // atom 2
    op += (size_t)2 * CSTRIDE;                                  // atom 3 row

    const float4* p = g_coef + chain;
    float4 buf[4];
#pragma unroll
    for (int u = 0; u < 4; ++u) buf[u] = __ldg(p + (size_t)u * CSTRIDE);

#pragma unroll 1
    for (int g = 0; g < 254; ++g) {          // 254*4 = 1016 steps
        const float4* pn = p + (size_t)4 * CSTRIDE;
#pragma unroll
        for (int u = 0; u < 4; ++u) {
            float4 cf = buf[u];
            buf[u] = __ldg(pn + (size_t)u * CSTRIDE);
            step_fn(cf, u1x, u1y, u1z, u2x, u2y, u2z, cx, cy, cz, op);
            op += (size_t)CSTRIDE;
        }
        p = pn;
    }
#pragma unroll
    for (int u = 0; u < 4; ++u) {            // steps 1016..1019
        step_fn(buf[u], u1x, u1y, u1z, u2x, u2y, u2z, cx, cy, cz, op);
        op += (size_t)CSTRIDE;
    }
    float4 last = __ldg(p + (size_t)4 * CSTRIDE);   // row 1020
    step_fn(last, u1x, u1y, u1z, u2x, u2y, u2z, cx, cy, cz, op);
}

// ---------------------------------------------------------------------------
// Reduce: sum |pred - targ|^2 over [1023][2048] float4 pairs; last block
// writes the mean. 67MB coalesced reads.
// ---------------------------------------------------------------------------
__global__ __launch_bounds__(256) void reduce_kernel(float* __restrict__ out)
{
    __shared__ double sh[256];
    int tid = threadIdx.x;
    float acc = 0.f;
    for (size_t i = (size_t)blockIdx.x * 256 + tid; i < (size_t)NPAIR;
         i += (size_t)gridDim.x * 256) {
        size_t r = i >> 11;
        size_t c = i & 2047;
        float4 pv = g_pos[r * CSTRIDE + c];
        float4 tv = g_pos[r * CSTRIDE + c + BROWS];
        float fx = pv.x - tv.x, fy = pv.y - tv.y, fz = pv.z - tv.z;
        acc = fmaf(fx, fx, acc);
        acc = fmaf(fy, fy, acc);
        acc = fmaf(fz, fz, acc);
    }
    sh[tid] = (double)acc;
    __syncthreads();
#pragma unroll
    for (int s = 128; s > 0; s >>= 1) {
        if (tid < s) sh[tid] += sh[tid + s];
        __syncthreads();
    }
    if (tid == 0) {
        atomicAdd(&g_acc, sh[0]);
        __threadfence();
        unsigned old = atomicAdd(&g_count, 1u);
        if (old == (unsigned)(gridDim.x - 1)) {
            double total;
            asm volatile("ld.global.cg.f64 %0, [%1];" : "=d"(total) : "l"(&g_acc));
            out[0] = (float)(total * (1.0 / (2048.0 * 1024.0 * 3.0)));
        }
    }
}

extern "C" void kernel_launch(void* const* d_in, const int* in_sizes, int n_in,
                              void* d_out, int out_size)
{
    const float* pred = (const float*)d_in[0];
    const float* targ = (const float*)d_in[1];
    float* out = (float*)d_out;

    dim3 pb(32, 32), pg(32, NCH / 32);
    prep_kernel<<<pg, pb>>>(pred, targ);
    scan_kernel<<<NCH / 32, 32>>>();
    reduce_kernel<<<1024, 256>>>(out);
}